// round 1
// baseline (speedup 1.0000x reference)
#include <cuda_runtime.h>
#include <cuda_bf16.h>

#define N_EXPERTS 32
#define H 256
#define BATCH 16
#define SEQ 8192
#define ALPHA 0.001f

// Scratch for aux-loss statistics (device globals: no allocation allowed).
__device__ float g_sums[BATCH * N_EXPERTS];   // sum of softmax scores per (batch, expert)
__device__ float g_cnts[BATCH * N_EXPERTS];   // top-1 assignment counts per (batch, expert)

__global__ void zero_kernel() {
    int i = threadIdx.x;                      // 512 threads
    g_sums[i] = 0.0f;
    g_cnts[i] = 0.0f;
}

// One block = 256 threads = 8 warps. Each warp processes 32 consecutive tokens,
// 2 tokens per iteration (T=2 smem-traffic batching). Block covers 256 tokens,
// all within a single batch (256 | 8192).
__global__ __launch_bounds__(256, 2)
void gate_kernel(const float* __restrict__ x, const float* __restrict__ w,
                 float* __restrict__ out_idx, float* __restrict__ out_w) {
    __shared__ float Ws[N_EXPERTS * H];       // 32 KB
    __shared__ float s_sum[N_EXPERTS];
    __shared__ float s_cnt[N_EXPERTS];

    const int tid = threadIdx.x;
    const int lane = tid & 31;
    const int warp = tid >> 5;

    // Stage gate weight into smem (vectorized).
    for (int i = tid; i < N_EXPERTS * H / 4; i += 256)
        ((float4*)Ws)[i] = ((const float4*)w)[i];
    if (tid < N_EXPERTS) { s_sum[tid] = 0.0f; s_cnt[tid] = 0.0f; }
    __syncthreads();

    const int tok_base = blockIdx.x * 256 + warp * 32;

    float lane_score_sum = 0.0f;   // lane e accumulates score_e over its 32 tokens
    float lane_cnt = 0.0f;         // lane e counts argmax==e over its 32 tokens
    float res_idx = 0.0f, res_w = 0.0f;   // coalesced-store staging: lane j holds token tok_base+j

    #pragma unroll 1
    for (int it = 0; it < 16; it++) {
        const int t0 = tok_base + 2 * it;

        // Load x chunks: lane owns x[t][lane*8 .. lane*8+8) for both tokens.
        const float4* xp0 = (const float4*)(x + (size_t)t0 * H);
        const float4* xp1 = (const float4*)(x + (size_t)(t0 + 1) * H);
        float4 xa0 = xp0[lane * 2], xb0 = xp0[lane * 2 + 1];
        float4 xa1 = xp1[lane * 2], xb1 = xp1[lane * 2 + 1];

        // Partial dots: p{0,1}[e] = <x_chunk, W[e]_chunk>
        float p0[N_EXPERTS], p1[N_EXPERTS];
        #pragma unroll
        for (int e = 0; e < N_EXPERTS; e++) {
            const float4 wa = *(const float4*)(Ws + e * H + lane * 8);
            const float4 wb = *(const float4*)(Ws + e * H + lane * 8 + 4);
            float a0 = xa0.x * wa.x;
            a0 = fmaf(xa0.y, wa.y, a0); a0 = fmaf(xa0.z, wa.z, a0); a0 = fmaf(xa0.w, wa.w, a0);
            a0 = fmaf(xb0.x, wb.x, a0); a0 = fmaf(xb0.y, wb.y, a0);
            a0 = fmaf(xb0.z, wb.z, a0); a0 = fmaf(xb0.w, wb.w, a0);
            p0[e] = a0;
            float a1 = xa1.x * wa.x;
            a1 = fmaf(xa1.y, wa.y, a1); a1 = fmaf(xa1.z, wa.z, a1); a1 = fmaf(xa1.w, wa.w, a1);
            a1 = fmaf(xb1.x, wb.x, a1); a1 = fmaf(xb1.y, wb.y, a1);
            a1 = fmaf(xb1.z, wb.z, a1); a1 = fmaf(xb1.w, wb.w, a1);
            p1[e] = a1;
        }

        // Butterfly reduce-transpose: 31 shfls/token -> lane holds logit[expert==lane].
        int n = N_EXPERTS;
        #pragma unroll
        for (int bit = 16; bit >= 1; bit >>= 1) {
            const bool up = (lane & bit) != 0;
            n >>= 1;
            #pragma unroll
            for (int i = 0; i < 16; i++) {
                if (i >= n) break;
                float give0 = up ? p0[i] : p0[i + n];
                float keep0 = up ? p0[i + n] : p0[i];
                p0[i] = keep0 + __shfl_xor_sync(0xffffffffu, give0, bit);
                float give1 = up ? p1[i] : p1[i + n];
                float keep1 = up ? p1[i + n] : p1[i];
                p1[i] = keep1 + __shfl_xor_sync(0xffffffffu, give1, bit);
            }
        }
        const float logit0 = p0[0];
        const float logit1 = p1[0];

        // ---- token 0: max+argmax, sum-exp, score ----
        {
            float m = logit0; int mi = lane;
            #pragma unroll
            for (int off = 16; off; off >>= 1) {
                float om = __shfl_xor_sync(0xffffffffu, m, off);
                int   oi = __shfl_xor_sync(0xffffffffu, mi, off);
                if (om > m || (om == m && oi < mi)) { m = om; mi = oi; }
            }
            float e = __expf(logit0 - m);
            float s = e;
            #pragma unroll
            for (int off = 16; off; off >>= 1) s += __shfl_xor_sync(0xffffffffu, s, off);
            lane_score_sum += e / s;
            if (lane == mi) lane_cnt += 1.0f;
            if (lane == 2 * it) { res_idx = (float)mi; res_w = 1.0f / s; }
        }
        // ---- token 1 ----
        {
            float m = logit1; int mi = lane;
            #pragma unroll
            for (int off = 16; off; off >>= 1) {
                float om = __shfl_xor_sync(0xffffffffu, m, off);
                int   oi = __shfl_xor_sync(0xffffffffu, mi, off);
                if (om > m || (om == m && oi < mi)) { m = om; mi = oi; }
            }
            float e = __expf(logit1 - m);
            float s = e;
            #pragma unroll
            for (int off = 16; off; off >>= 1) s += __shfl_xor_sync(0xffffffffu, s, off);
            lane_score_sum += e / s;
            if (lane == mi) lane_cnt += 1.0f;
            if (lane == 2 * it + 1) { res_idx = (float)mi; res_w = 1.0f / s; }
        }
    }

    // Coalesced result stores: lane j holds token tok_base+j.
    out_idx[tok_base + lane] = res_idx;
    out_w[tok_base + lane] = res_w;

    // Block-level aux accumulation (8 smem atomics per expert).
    atomicAdd(&s_sum[lane], lane_score_sum);
    atomicAdd(&s_cnt[lane], lane_cnt);
    __syncthreads();
    if (tid < N_EXPERTS) {
        const int batch = blockIdx.x >> 5;   // 32 blocks per batch (256 tokens each)
        atomicAdd(&g_sums[batch * N_EXPERTS + tid], s_sum[tid]);
        atomicAdd(&g_cnts[batch * N_EXPERTS + tid], s_cnt[tid]);
    }
}

__global__ void aux_kernel(float* __restrict__ out_aux) {
    const int i = threadIdx.x;   // 512 threads = BATCH*N_EXPERTS
    float v = (g_cnts[i] * ((float)N_EXPERTS / (float)SEQ)) *
              (g_sums[i] * (1.0f / (float)SEQ));
    #pragma unroll
    for (int off = 16; off; off >>= 1) v += __shfl_xor_sync(0xffffffffu, v, off);
    __shared__ float red[16];
    if ((i & 31) == 0) red[i >> 5] = v;
    __syncthreads();
    if (i < 32) {
        float t = (i < 16) ? red[i] : 0.0f;
        #pragma unroll
        for (int off = 16; off; off >>= 1) t += __shfl_xor_sync(0xffffffffu, t, off);
        if (i == 0) out_aux[0] = t * (ALPHA / (float)BATCH);
    }
}

extern "C" void kernel_launch(void* const* d_in, const int* in_sizes, int n_in,
                              void* d_out, int out_size) {
    const float* x = (const float*)d_in[0];   // [16, 8192, 256] f32
    const float* w = (const float*)d_in[1];   // [32, 256] f32
    float* out = (float*)d_out;               // [N idx | N weight | 1 aux], f32

    const int n_tokens = in_sizes[0] / H;     // 131072
    const int n_blocks = n_tokens / 256;      // 512

    zero_kernel<<<1, BATCH * N_EXPERTS>>>();
    gate_kernel<<<n_blocks, 256>>>(x, w, out, out + n_tokens);
    aux_kernel<<<1, BATCH * N_EXPERTS>>>(out + 2 * n_tokens);
}